// round 7
// baseline (speedup 1.0000x reference)
#include <cuda_runtime.h>
#include <cstdint>

#define NBLK 128
#define NTHR 256
#define HDIM 512
#define BDIM 128
#define TIN  512
#define TOT  544
#define BH   (BDIM*HDIM)
#define SMEM_BYTES (26560*4)

__device__ float    g_h1[2*BH];
__device__ float    g_h2[2*BH];
__device__ unsigned g_bar;

static __device__ __forceinline__ unsigned long long mk64(unsigned lo, unsigned hi){
    unsigned long long r;
    asm("mov.b64 %0, {%1, %2};" : "=l"(r) : "r"(lo), "r"(hi));
    return r;
}
static __device__ __forceinline__ void fma2(unsigned long long& d,
                                            unsigned long long a, unsigned long long b){
    asm("fma.rn.f32x2 %0, %1, %2, %0;" : "+l"(d) : "l"(a), "l"(b));
}
static __device__ __forceinline__ float hsum2(unsigned long long v){
    unsigned lo, hi;
    asm("mov.b64 {%0, %1}, %2;" : "=r"(lo), "=r"(hi) : "l"(v));
    return __uint_as_float(lo) + __uint_as_float(hi);
}
static __device__ __forceinline__ float sigf(float x){ return 1.0f/(1.0f+__expf(-x)); }

static __device__ __forceinline__ void grid_barrier(unsigned& gen){
    __threadfence();
    __syncthreads();
    if (threadIdx.x == 0){
        unsigned target = gen + NBLK;
        atomicAdd(&g_bar, 1u);
        unsigned v;
        do { asm volatile("ld.acquire.gpu.u32 %0, [%1];" : "=r"(v) : "l"(&g_bar)); }
        while (v < target);
    }
    gen += NBLK;
    __syncthreads();
}

// Accumulate 4 gate rows (one hidden unit u) x 2 batch cols over K=512.
static __device__ __forceinline__ void gemm_acc(
    const float* __restrict__ wsm, const float* __restrict__ hsrc,
    unsigned long long (&acc)[4][2], int u, int b0, int b1)
{
    const ulonglong2* w2 = reinterpret_cast<const ulonglong2*>(wsm);
    const uint4* hA = reinterpret_cast<const uint4*>(hsrc) + (size_t)b0*(HDIM/4);
    const uint4* hB = reinterpret_cast<const uint4*>(hsrc) + (size_t)b1*(HDIM/4);
    const int sw = u << 1;
    #pragma unroll 4
    for (int k4 = 0; k4 < HDIM/4; ++k4){
        uint4 ha = __ldcg(hA + k4);
        uint4 hb = __ldcg(hB + k4);
        unsigned long long alo = mk64(ha.x, ha.y), ahi = mk64(ha.z, ha.w);
        unsigned long long blo = mk64(hb.x, hb.y), bhi = mk64(hb.z, hb.w);
        const int ks = k4 ^ sw;
        #pragma unroll
        for (int g = 0; g < 4; ++g){
            ulonglong2 w = w2[(u*4 + g)*128 + ks];
            fma2(acc[g][0], w.x, alo); fma2(acc[g][0], w.y, ahi);
            fma2(acc[g][1], w.x, blo); fma2(acc[g][1], w.y, bhi);
        }
    }
}

static __device__ __forceinline__ void out_one(
    const float* __restrict__ h2r, const float* __restrict__ s_wout,
    float bout, int b, float* dst)
{
    const int lane = threadIdx.x;  // caller: tid < 32
    const uint4*  hp = reinterpret_cast<const uint4*>(h2r) + (size_t)b*(HDIM/4);
    const float4* wp = reinterpret_cast<const float4*>(s_wout);
    float s = 0.f;
    #pragma unroll
    for (int q = lane; q < HDIM/4; q += 32){
        uint4 hv = __ldcg(hp + q); float4 w = wp[q];
        s += __uint_as_float(hv.x)*w.x + __uint_as_float(hv.y)*w.y
           + __uint_as_float(hv.z)*w.z + __uint_as_float(hv.w)*w.w;
    }
    #pragma unroll
    for (int o = 16; o; o >>= 1) s += __shfl_xor_sync(0xffffffffu, s, o);
    if (lane == 0) *dst = s + bout;
}

__global__ void lstm_reset(){ g_bar = 0u; }

__global__ void __launch_bounds__(NTHR, 1) lstm_persist(
    const float* __restrict__ xg,
    const float* __restrict__ Wih1, const float* __restrict__ Whh1,
    const float* __restrict__ bih1, const float* __restrict__ bhh1,
    const float* __restrict__ Wih2, const float* __restrict__ Whh2,
    const float* __restrict__ bih2, const float* __restrict__ bhh2,
    const float* __restrict__ Wout, const float* __restrict__ boutp,
    float* __restrict__ outg)
{
    extern __shared__ float sm[];
    float* s_ws1  = sm;               // 16x512 swizzled
    float* s_ws2i = sm + 8192;
    float* s_ws2h = sm + 16384;
    float* s_wout = sm + 24576;       // 512
    float* s_wih1 = sm + 25088;       // 16
    float* s_b1   = sm + 25104;
    float* s_b2   = sm + 25120;
    float* s_c1   = sm + 25136;       // 512
    float* s_c2   = sm + 25648;       // 512
    float* s_xs   = sm + 26160;       // 128
    float* s_red  = sm + 26288;       // 256
    float* s_bout = sm + 26544;

    const int tid = threadIdx.x;
    const int blk = blockIdx.x;
    const int U0  = blk * 4;
    const int u   = tid & 3;
    const int bg  = tid >> 2;
    const int b0  = bg*2, b1v = b0 + 1;

    // one-time staging
    {
        float4* w1v  = reinterpret_cast<float4*>(s_ws1);
        float4* w2iv = reinterpret_cast<float4*>(s_ws2i);
        float4* w2hv = reinterpret_cast<float4*>(s_ws2h);
        for (int idx = tid; idx < 16*128; idx += NTHR){
            int r = idx >> 7, k4 = idx & 127;
            int j = (r & 3)*512 + U0 + (r >> 2);
            int d = r*128 + (k4 ^ ((r >> 2) << 1));
            w1v [d] = reinterpret_cast<const float4*>(Whh1 + (size_t)j*512)[k4];
            w2iv[d] = reinterpret_cast<const float4*>(Wih2 + (size_t)j*512)[k4];
            w2hv[d] = reinterpret_cast<const float4*>(Whh2 + (size_t)j*512)[k4];
        }
        if (tid < 16){
            int j = (tid & 3)*512 + U0 + (tid >> 2);
            s_wih1[tid] = Wih1[j];
            s_b1[tid]   = bih1[j] + bhh1[j];
            s_b2[tid]   = bih2[j] + bhh2[j];
        }
        if (tid < 128)
            reinterpret_cast<float4*>(s_wout)[tid] =
                reinterpret_cast<const float4*>(Wout)[tid];
        if (tid == 0) s_bout[0] = boutp[0];
        s_c1[tid] = 0.f; s_c1[tid+256] = 0.f;
        s_c2[tid] = 0.f; s_c2[tid+256] = 0.f;
        for (int i = tid; i < 512; i += NTHR){
            size_t o = (size_t)blk*512 + i;
            g_h1[o] = 0.f; g_h1[BH+o] = 0.f;
            g_h2[o] = 0.f; g_h2[BH+o] = 0.f;
        }
    }
    unsigned gen = 0;
    grid_barrier(gen);

    for (int t = 0; t < TOT; ++t){
        const int cur = t & 1, prv = cur ^ 1;
        const float* h1r = g_h1 + (size_t)prv*BH;
        float*       h1w = g_h1 + (size_t)cur*BH;
        const float* h2r = g_h2 + (size_t)prv*BH;
        float*       h2w = g_h2 + (size_t)cur*BH;

        // Phase X: x_t into s_xs; emit out(t-1)
        if (t < TIN){
            if (tid < BDIM) s_xs[tid] = xg[(size_t)tid*TIN + t];
            if (t > 0 && tid < 32)
                out_one(h2r, s_wout, s_bout[0], blk, outg + (size_t)blk*TOT + (t-1));
        } else {
            int b = tid >> 1, hf = tid & 1;
            const uint4*  hp = reinterpret_cast<const uint4*>(h2r)
                               + (size_t)b*(HDIM/4) + hf*(HDIM/8);
            const float4* wp = reinterpret_cast<const float4*>(s_wout) + hf*(HDIM/8);
            float s = 0.f;
            #pragma unroll 8
            for (int q = 0; q < HDIM/8; ++q){
                uint4 hv = __ldcg(hp + q); float4 w = wp[q];
                s += __uint_as_float(hv.x)*w.x + __uint_as_float(hv.y)*w.y
                   + __uint_as_float(hv.z)*w.z + __uint_as_float(hv.w)*w.w;
            }
            s_red[tid] = s;
            __syncthreads();
            if (tid < BDIM) s_xs[tid] = s_red[2*tid] + s_red[2*tid+1] + s_bout[0];
        }
        __syncthreads();
        if (t >= TIN && tid == 0) outg[(size_t)blk*TOT + (t-1)] = s_xs[blk];

        // Phase 1: layer-1
        {
            unsigned long long acc[4][2] = {};
            gemm_acc(s_ws1, h1r, acc, u, b0, b1v);
            #pragma unroll
            for (int bi = 0; bi < 2; ++bi){
                int b = b0 + bi;
                float xv = s_xs[b];
                float vi = hsum2(acc[0][bi]) + s_b1[u*4+0] + xv*s_wih1[u*4+0];
                float vf = hsum2(acc[1][bi]) + s_b1[u*4+1] + xv*s_wih1[u*4+1];
                float vg = hsum2(acc[2][bi]) + s_b1[u*4+2] + xv*s_wih1[u*4+2];
                float vo = hsum2(acc[3][bi]) + s_b1[u*4+3] + xv*s_wih1[u*4+3];
                float c  = sigf(vf)*s_c1[u*BDIM+b] + sigf(vi)*tanhf(vg);
                s_c1[u*BDIM+b] = c;
                h1w[(size_t)b*HDIM + U0 + u] = sigf(vo)*tanhf(c);
            }
        }
        grid_barrier(gen);

        // Phase 2: layer-2 (K = h1_new then h2_prev)
        {
            unsigned long long acc[4][2] = {};
            gemm_acc(s_ws2i, h1w, acc, u, b0, b1v);
            gemm_acc(s_ws2h, h2r, acc, u, b0, b1v);
            #pragma unroll
            for (int bi = 0; bi < 2; ++bi){
                int b = b0 + bi;
                float vi = hsum2(acc[0][bi]) + s_b2[u*4+0];
                float vf = hsum2(acc[1][bi]) + s_b2[u*4+1];
                float vg = hsum2(acc[2][bi]) + s_b2[u*4+2];
                float vo = hsum2(acc[3][bi]) + s_b2[u*4+3];
                float c  = sigf(vf)*s_c2[u*BDIM+b] + sigf(vi)*tanhf(vg);
                s_c2[u*BDIM+b] = c;
                h2w[(size_t)b*HDIM + U0 + u] = sigf(vo)*tanhf(c);
            }
        }
        grid_barrier(gen);
    }

    if (tid < 32)
        out_one(g_h2 + (size_t)((TOT-1)&1)*BH, s_wout, s_bout[0],
                blk, outg + (size_t)blk*TOT + (TOT-1));
}

extern "C" void kernel_launch(void* const* d_in, const int* in_sizes, int n_in,
                              void* d_out, int out_size){
    (void)in_sizes; (void)n_in; (void)out_size;
    static int smem_ok = 0;
    if (!smem_ok){
        cudaFuncSetAttribute(lstm_persist,
                             cudaFuncAttributeMaxDynamicSharedMemorySize, SMEM_BYTES);
        smem_ok = 1;
    }
    const float* x    = (const float*)d_in[0];
    const float* Wih1 = (const float*)d_in[1];
    const float* Whh1 = (const float*)d_in[2];
    const float* bih1 = (const float*)d_in[3];
    const float* bhh1 = (const float*)d_in[4];
    const float* Wih2 = (const float*)d_in[5];
    const float* Whh2 = (const float*)d_in[6];
    const float* bih2 = (const float*)d_in[7];
    const float* bhh2 = (const float*)d_in[8];
    const float* Wout = (const float*)d_in[9];
    const float* bout = (const float*)d_in[10];
    float* out = (float*)d_out;

    lstm_reset<<<1, 1>>>();
    lstm_persist<<<NBLK, NTHR, SMEM_BYTES>>>(
        x, Wih1, Whh1, bih1, bhh1, Wih2, Whh2, bih2, bhh2, Wout, bout, out);
}